// round 1
// baseline (speedup 1.0000x reference)
#include <cuda_runtime.h>
#include <stdint.h>

#define BATCH 8192
#define IN_F  16384
#define HID   384
#define NOUT  10
#define KW    (IN_F / 32)   // 512 words per row

// ---------------- scratch (no allocation allowed -> __device__ globals) ----
__device__ uint32_t  g_xbits[(size_t)BATCH * KW];   // 16 MB
__device__ uint32_t  g_wbits[(size_t)HID * KW];     // 768 KB
__device__ int       g_h[(size_t)BATCH * HID];      // 12.6 MB
__device__ long long g_sum[HID];
__device__ long long g_sumsq[HID];
__device__ float     g_A[HID];
__device__ float     g_B[HID];

// ---------------- zero the BN accumulators (graph replays reuse globals) ---
__global__ void zero_sums_kernel() {
    int j = threadIdx.x;
    if (j < HID) { g_sum[j] = 0; g_sumsq[j] = 0; }
}

// ---------------- sign bit-packing: 1 warp packs 128 floats -> 4 words -----
// Bit permutation within each 128-float group is arbitrary but IDENTICAL for
// x and W1, so XOR+popcount dot products are unaffected.
__global__ void pack_kernel(const float* __restrict__ in, int which) {
    int t    = blockIdx.x * blockDim.x + threadIdx.x;
    int warp = t >> 5;
    int lane = t & 31;
    float4 v = reinterpret_cast<const float4*>(in)[(size_t)warp * 32 + lane];
    unsigned b0 = __ballot_sync(0xffffffffu, v.x < 0.f);
    unsigned b1 = __ballot_sync(0xffffffffu, v.y < 0.f);
    unsigned b2 = __ballot_sync(0xffffffffu, v.z < 0.f);
    unsigned b3 = __ballot_sync(0xffffffffu, v.w < 0.f);
    if (lane == 0) {
        uint4 w = make_uint4(b0, b1, b2, b3);
        uint32_t* dst = which ? g_wbits : g_xbits;
        reinterpret_cast<uint4*>(dst)[warp] = w;
    }
}

// ---------------- binarized GEMM: h[b][j] = 16384 - 2*sum popc(x^w) --------
#define TM 64
#define TN 64
#define TKC 32

__global__ __launch_bounds__(256) void gemm_kernel() {
    __shared__ uint32_t sx[TM][TKC + 1];   // +1 pad kills sw bank conflicts
    __shared__ uint32_t sw[TN][TKC + 1];

    const int m0  = blockIdx.x * TM;
    const int n0  = blockIdx.y * TN;
    const int tid = threadIdx.x;
    const int tx  = tid & 15;   // 16 col groups
    const int ty  = tid >> 4;   // 16 row groups

    int acc[4][4];
#pragma unroll
    for (int i = 0; i < 4; i++)
#pragma unroll
        for (int j = 0; j < 4; j++) acc[i][j] = 0;

    for (int k0 = 0; k0 < KW; k0 += TKC) {
        // Cooperative tile load: 512 uint4 per tile, 2 per thread, coalesced.
#pragma unroll
        for (int q = 0; q < 2; q++) {
            int v   = tid + 256 * q;
            int row = v >> 3;
            int kq  = (v & 7) * 4;
            uint4 dx = *reinterpret_cast<const uint4*>(
                &g_xbits[(size_t)(m0 + row) * KW + k0 + kq]);
            sx[row][kq + 0] = dx.x; sx[row][kq + 1] = dx.y;
            sx[row][kq + 2] = dx.z; sx[row][kq + 3] = dx.w;
            uint4 dw = *reinterpret_cast<const uint4*>(
                &g_wbits[(size_t)(n0 + row) * KW + k0 + kq]);
            sw[row][kq + 0] = dw.x; sw[row][kq + 1] = dw.y;
            sw[row][kq + 2] = dw.z; sw[row][kq + 3] = dw.w;
        }
        __syncthreads();

#pragma unroll 8
        for (int k = 0; k < TKC; k++) {
            uint32_t a[4], b[4];
#pragma unroll
            for (int i = 0; i < 4; i++) a[i] = sx[ty * 4 + i][k];
#pragma unroll
            for (int j = 0; j < 4; j++) b[j] = sw[tx * 4 + j][k];
#pragma unroll
            for (int i = 0; i < 4; i++)
#pragma unroll
                for (int j = 0; j < 4; j++)
                    acc[i][j] += __popc(a[i] ^ b[j]);
        }
        __syncthreads();
    }

#pragma unroll
    for (int i = 0; i < 4; i++)
#pragma unroll
        for (int j = 0; j < 4; j++)
            g_h[(size_t)(m0 + ty * 4 + i) * HID + n0 + tx * 4 + j] =
                IN_F - 2 * acc[i][j];
}

// ---------------- BN batch statistics: exact integer sums (deterministic) --
__global__ void stats_kernel() {
    const int cg = blockIdx.x;        // 12 column groups of 32
    const int rc = blockIdx.y;        // 8 row chunks of 1024
    const int c  = threadIdx.x & 31;
    const int t  = threadIdx.x >> 5;  // 0..7
    const int col = cg * 32 + c;

    int s = 0;                        // |h|<=16384, 128 terms -> fits int32
    long long s2 = 0;
    const int rbase = rc * 1024;
    for (int r = rbase + t; r < rbase + 1024; r += 8) {
        int v = g_h[(size_t)r * HID + col];
        s  += v;
        s2 += (long long)v * v;
    }
    __shared__ int       ss [8][32];
    __shared__ long long ss2[8][32];
    ss[t][c] = s; ss2[t][c] = s2;
    __syncthreads();
    if (t == 0) {
        long long S = 0, S2 = 0;
#pragma unroll
        for (int u = 0; u < 8; u++) { S += ss[u][c]; S2 += ss2[u][c]; }
        atomicAdd((unsigned long long*)&g_sum[col],   (unsigned long long)S);
        atomicAdd((unsigned long long*)&g_sumsq[col], (unsigned long long)S2);
    }
}

// ---------------- fold BN into affine h*A + B --------------------------------
__global__ void finalize_kernel(const float* __restrict__ gamma,
                                const float* __restrict__ beta) {
    int j = blockIdx.x * blockDim.x + threadIdx.x;
    if (j >= HID) return;
    double mean = (double)g_sum[j]   / (double)BATCH;
    double var  = (double)g_sumsq[j] / (double)BATCH - mean * mean;
    float a = gamma[j] * (float)(1.0 / sqrt(var + 1e-5));
    g_A[j] = a;
    g_B[j] = beta[j] - (float)mean * a;
}

// ---------------- output layer: one warp per batch row -----------------------
// sign(clip(v)) == sign(v); hardtanh never flips sign.
__global__ __launch_bounds__(256) void out_kernel(const float* __restrict__ W4,
                                                  float* __restrict__ out) {
    int gt   = blockIdx.x * blockDim.x + threadIdx.x;
    int row  = gt >> 5;
    int lane = gt & 31;
    if (row >= BATCH) return;

    float acc[NOUT];
#pragma unroll
    for (int o = 0; o < NOUT; o++) acc[o] = 0.f;

    for (int j = lane; j < HID; j += 32) {
        float v = (float)g_h[(size_t)row * HID + j] * g_A[j] + g_B[j];
        float s = (v > 0.f) ? 1.f : ((v < 0.f) ? -1.f : 0.f);
#pragma unroll
        for (int o = 0; o < NOUT; o++) {
            float w  = __ldg(&W4[o * HID + j]);
            float ws = (w > 0.f) ? 1.f : ((w < 0.f) ? -1.f : 0.f);
            acc[o] = fmaf(s, ws, acc[o]);
        }
    }
#pragma unroll
    for (int o = 0; o < NOUT; o++)
#pragma unroll
        for (int off = 16; off; off >>= 1)
            acc[o] += __shfl_down_sync(0xffffffffu, acc[o], off);

    if (lane == 0) {
#pragma unroll
        for (int o = 0; o < NOUT; o++) out[(size_t)row * NOUT + o] = acc[o];
    }
}

// ---------------- launch ----------------------------------------------------
extern "C" void kernel_launch(void* const* d_in, const int* in_sizes, int n_in,
                              void* d_out, int out_size) {
    const float* x     = (const float*)d_in[0];
    const float* W1    = (const float*)d_in[1];
    const float* gamma = (const float*)d_in[2];
    const float* beta  = (const float*)d_in[3];
    const float* W4    = (const float*)d_in[4];
    float* out = (float*)d_out;

    zero_sums_kernel<<<1, HID>>>();

    // x: 8192*16384 floats -> 1,048,576 warps -> 131072 blocks of 8 warps
    pack_kernel<<<(BATCH * (IN_F / 128)) / 8, 256>>>(x, 0);
    // W1: 384*16384 floats -> 49,152 warps -> 6144 blocks
    pack_kernel<<<(HID * (IN_F / 128)) / 8, 256>>>(W1, 1);

    dim3 ggrid(BATCH / TM, HID / TN);   // (128, 6)
    gemm_kernel<<<ggrid, 256>>>();

    stats_kernel<<<dim3(HID / 32, BATCH / 1024), 256>>>();   // (12, 8)
    finalize_kernel<<<1, HID>>>(gamma, beta);

    out_kernel<<<(BATCH * 32) / 256, 256>>>(W4, out);        // 1024 blocks
}